// round 11
// baseline (speedup 1.0000x reference)
#include <cuda_runtime.h>
#include <stdint.h>

#define NN 50000
#define EE 1600000
#define DIM 128
#define HEADS 4
#define EDIM 16

// ---------------- scratch (device globals: allocation-free) ----------------
__device__ __align__(16) float g_xl[(size_t)NN * DIM];      // x @ W_l + b_l
__device__ __align__(16) float g_xr[(size_t)NN * DIM];      // x @ W_r + b_r
__device__ __align__(16) float g_logits[(size_t)EE * HEADS];// logits, then exp()
__device__ __align__(16) unsigned int g_menc[NN * HEADS];   // ordered-uint max
__device__ __align__(16) float g_denom[NN * HEADS];         // softmax denom
__device__ __align__(16) float g_accum[(size_t)NN * DIM];   // aggregated msgs
__device__ int g_idx64;                                     // edge_index dtype flag

// ---------------- helpers ----------------
__device__ __forceinline__ unsigned enc_f(float f) {
    unsigned u = __float_as_uint(f);
    return (u & 0x80000000u) ? ~u : (u | 0x80000000u);
}
__device__ __forceinline__ float dec_f(unsigned e) {
    return __uint_as_float((e & 0x80000000u) ? (e & 0x7FFFFFFFu) : ~e);
}
__device__ __forceinline__ void atomicAddF4(float* addr, float4 v) {
#if __CUDA_ARCH__ >= 900
    atomicAdd(reinterpret_cast<float4*>(addr), v);
#else
    atomicAdd(addr + 0, v.x); atomicAdd(addr + 1, v.y);
    atomicAdd(addr + 2, v.z); atomicAdd(addr + 3, v.w);
#endif
}

// ---------------- K0: detect int64 vs int32 edge_index ----------------
__global__ void k_detect(const void* __restrict__ ei) {
    if (threadIdx.x == 0 && blockIdx.x == 0) {
        const long long* p = (const long long*)ei;
        int ok = 1;
        #pragma unroll 4
        for (int i = 0; i < 64; i++) {
            long long v = p[i];
            if (v < 0 || v >= NN) ok = 0;
        }
        g_idx64 = ok;
    }
}

// ---------------- K0b: zero accumulators ----------------
__global__ void k_zero() {
    size_t i = (size_t)blockIdx.x * blockDim.x + threadIdx.x;
    size_t stride = (size_t)gridDim.x * blockDim.x;
    for (size_t j = i; j < (size_t)NN * DIM; j += stride) g_accum[j] = 0.0f;
    for (size_t j = i; j < (size_t)NN * HEADS; j += stride) {
        g_denom[j] = 0.0f;
        g_menc[j] = 0u;   // below enc(-inf), never wins a max for real edges
    }
}

// ---------------- K1: fused GEMM  x@[W_l | W_r] + [b_l | b_r] ----------------
// Block: 256 threads = 64 col-groups (4 cols each) x 4 row-groups (4 rows each)
// Tile: 16 rows x 256 cols, K-chunked by 32.
__global__ __launch_bounds__(256) void k_gemm(
    const float* __restrict__ x,
    const float* __restrict__ Wl, const float* __restrict__ bl,
    const float* __restrict__ Wr, const float* __restrict__ br)
{
    constexpr int KC = 32;
    __shared__ __align__(16) float Ws[KC][256];
    __shared__ __align__(16) float xs[KC][16];

    const int t  = threadIdx.x;
    const int cx = t & 63;        // col group: cols 4*cx .. 4*cx+3 (of 256)
    const int cy = t >> 6;        // row group: rows 4*cy .. 4*cy+3 (of 16)
    const int row0 = blockIdx.x * 16;

    float acc[4][4];
    #pragma unroll
    for (int i = 0; i < 4; i++)
        #pragma unroll
        for (int j = 0; j < 4; j++) acc[i][j] = 0.0f;

    for (int k0 = 0; k0 < DIM; k0 += KC) {
        // load W chunk: KC x 256 (W_l cols 0..127, W_r cols 128..255)
        #pragma unroll
        for (int i = t; i < KC * 64; i += 256) {
            int k  = i >> 6;
            int c4 = (i & 63) * 4;
            const float* srcp = (c4 < 128) ? &Wl[(k0 + k) * 128 + c4]
                                           : &Wr[(k0 + k) * 128 + (c4 - 128)];
            *(float4*)&Ws[k][c4] = *(const float4*)srcp;
        }
        // load x chunk transposed: xs[k][r]
        if (t < 128) {
            int r  = t >> 3;
            int kq = (t & 7) * 4;
            float4 v = *(const float4*)&x[(size_t)(row0 + r) * DIM + k0 + kq];
            xs[kq + 0][r] = v.x; xs[kq + 1][r] = v.y;
            xs[kq + 2][r] = v.z; xs[kq + 3][r] = v.w;
        }
        __syncthreads();

        #pragma unroll
        for (int k = 0; k < KC; k++) {
            float4 w  = *(const float4*)&Ws[k][cx << 2];
            float4 xv = *(const float4*)&xs[k][cy << 2];
            acc[0][0] = fmaf(xv.x, w.x, acc[0][0]); acc[0][1] = fmaf(xv.x, w.y, acc[0][1]);
            acc[0][2] = fmaf(xv.x, w.z, acc[0][2]); acc[0][3] = fmaf(xv.x, w.w, acc[0][3]);
            acc[1][0] = fmaf(xv.y, w.x, acc[1][0]); acc[1][1] = fmaf(xv.y, w.y, acc[1][1]);
            acc[1][2] = fmaf(xv.y, w.z, acc[1][2]); acc[1][3] = fmaf(xv.y, w.w, acc[1][3]);
            acc[2][0] = fmaf(xv.z, w.x, acc[2][0]); acc[2][1] = fmaf(xv.z, w.y, acc[2][1]);
            acc[2][2] = fmaf(xv.z, w.z, acc[2][2]); acc[2][3] = fmaf(xv.z, w.w, acc[2][3]);
            acc[3][0] = fmaf(xv.w, w.x, acc[3][0]); acc[3][1] = fmaf(xv.w, w.y, acc[3][1]);
            acc[3][2] = fmaf(xv.w, w.z, acc[3][2]); acc[3][3] = fmaf(xv.w, w.w, acc[3][3]);
        }
        __syncthreads();
    }

    // epilogue: bias + store
    const int c4 = cx * 4;
    #pragma unroll
    for (int r = 0; r < 4; r++) {
        size_t row = (size_t)(row0 + cy * 4 + r);
        if (c4 < 128) {
            float4 o = make_float4(acc[r][0] + bl[c4],     acc[r][1] + bl[c4 + 1],
                                   acc[r][2] + bl[c4 + 2], acc[r][3] + bl[c4 + 3]);
            *(float4*)&g_xl[row * DIM + c4] = o;
        } else {
            int c = c4 - 128;
            float4 o = make_float4(acc[r][0] + br[c],     acc[r][1] + br[c + 1],
                                   acc[r][2] + br[c + 2], acc[r][3] + br[c + 3]);
            *(float4*)&g_xr[row * DIM + c] = o;
        }
    }
}

// ---------------- K2: edge attention logits + segment max ----------------
// One warp per edge; lane = channel c within each head; j = head.
__global__ __launch_bounds__(256) void k_logits(
    const void* __restrict__ ei, const float* __restrict__ eattr,
    const float* __restrict__ We, const float* __restrict__ att)
{
    __shared__ float Wes[EDIM][DIM];
    __shared__ float atts[DIM];
    const int t = threadIdx.x, lane = t & 31, w = t >> 5;

    for (int i = t; i < EDIM * DIM; i += 256) Wes[i >> 7][i & 127] = We[i];
    if (t < DIM) atts[t] = att[t];
    __syncthreads();

    const int e = blockIdx.x * 8 + w;
    const int is64 = g_idx64;
    int s = 0, d = 0;
    if (lane == 0) {
        if (is64) {
            const long long* p = (const long long*)ei;
            s = (int)p[e]; d = (int)p[(size_t)EE + e];
        } else {
            const int* p = (const int*)ei;
            s = p[e]; d = p[(size_t)EE + e];
        }
    }
    s = __shfl_sync(0xffffffffu, s, 0);
    d = __shfl_sync(0xffffffffu, d, 0);

    // e_f = edge_attr[e] @ W_e (each lane computes 4 channels, one per head)
    float ea = (lane < EDIM) ? __ldg(&eattr[(size_t)e * EDIM + lane]) : 0.0f;
    float ef0 = 0.f, ef1 = 0.f, ef2 = 0.f, ef3 = 0.f;
    #pragma unroll
    for (int dd = 0; dd < EDIM; dd++) {
        float a = __shfl_sync(0xffffffffu, ea, dd);
        ef0 = fmaf(a, Wes[dd][lane],      ef0);
        ef1 = fmaf(a, Wes[dd][lane + 32], ef1);
        ef2 = fmaf(a, Wes[dd][lane + 64], ef2);
        ef3 = fmaf(a, Wes[dd][lane + 96], ef3);
    }

    const float* xl = g_xl + (size_t)s * DIM;
    const float* xr = g_xr + (size_t)d * DIM;
    float z0 = __ldg(xl + lane)      + __ldg(xr + lane)      + ef0;
    float z1 = __ldg(xl + lane + 32) + __ldg(xr + lane + 32) + ef1;
    float z2 = __ldg(xl + lane + 64) + __ldg(xr + lane + 64) + ef2;
    float z3 = __ldg(xl + lane + 96) + __ldg(xr + lane + 96) + ef3;
    z0 = (z0 >= 0.f) ? z0 : 0.2f * z0;
    z1 = (z1 >= 0.f) ? z1 : 0.2f * z1;
    z2 = (z2 >= 0.f) ? z2 : 0.2f * z2;
    z3 = (z3 >= 0.f) ? z3 : 0.2f * z3;
    float p0 = z0 * atts[lane];
    float p1 = z1 * atts[lane + 32];
    float p2 = z2 * atts[lane + 64];
    float p3 = z3 * atts[lane + 96];

    #pragma unroll
    for (int off = 16; off; off >>= 1) {
        p0 += __shfl_xor_sync(0xffffffffu, p0, off);
        p1 += __shfl_xor_sync(0xffffffffu, p1, off);
        p2 += __shfl_xor_sync(0xffffffffu, p2, off);
        p3 += __shfl_xor_sync(0xffffffffu, p3, off);
    }

    float myp = (lane == 1) ? p1 : (lane == 2) ? p2 : (lane == 3) ? p3 : p0;
    if (lane < 4) {
        g_logits[(size_t)e * HEADS + lane] = myp;
        atomicMax(&g_menc[d * HEADS + lane], enc_f(myp));
    }
}

// ---------------- K3: exp(logit - m) + segment sum (denominator) ----------------
__global__ __launch_bounds__(256) void k_exp(const void* __restrict__ ei) {
    const int e = blockIdx.x * 256 + threadIdx.x;
    int d;
    if (g_idx64) d = (int)((const long long*)ei)[(size_t)EE + e];
    else         d = ((const int*)ei)[(size_t)EE + e];

    float4 lg = *((const float4*)g_logits + e);
    const unsigned* mp = &g_menc[d * HEADS];
    float4 ex = make_float4(expf(lg.x - dec_f(mp[0])),
                            expf(lg.y - dec_f(mp[1])),
                            expf(lg.z - dec_f(mp[2])),
                            expf(lg.w - dec_f(mp[3])));
    *((float4*)g_logits + e) = ex;
    atomicAddF4(&g_denom[d * HEADS], ex);
}

// ---------------- K4: weighted message aggregation ----------------
// One warp per edge; lane handles 4 consecutive channels (head = lane>>3).
__global__ __launch_bounds__(256) void k_aggr(const void* __restrict__ ei) {
    const int t = threadIdx.x, lane = t & 31, w = t >> 5;
    const int e = blockIdx.x * 8 + w;
    int s = 0, d = 0;
    if (lane == 0) {
        if (g_idx64) {
            const long long* p = (const long long*)ei;
            s = (int)p[e]; d = (int)p[(size_t)EE + e];
        } else {
            const int* p = (const int*)ei;
            s = p[e]; d = p[(size_t)EE + e];
        }
    }
    s = __shfl_sync(0xffffffffu, s, 0);
    d = __shfl_sync(0xffffffffu, d, 0);

    const int h = lane >> 3;
    float ex  = __ldg(&g_logits[(size_t)e * HEADS + h]);
    float den = __ldg(&g_denom[d * HEADS + h]);
    float alpha = ex / (den + 1e-16f);

    float4 xv = *(const float4*)&g_xl[(size_t)s * DIM + lane * 4];
    float4 msg = make_float4(xv.x * alpha, xv.y * alpha, xv.z * alpha, xv.w * alpha);
    atomicAddF4(&g_accum[(size_t)d * DIM + lane * 4], msg);
}

// ---------------- K5: +bias, LayerNorm, ReLU, residual ----------------
__global__ __launch_bounds__(256) void k_ln(
    const float* __restrict__ x, const float* __restrict__ cbias,
    const float* __restrict__ gamma, const float* __restrict__ beta,
    float* __restrict__ out)
{
    const int t = threadIdx.x, lane = t & 31, w = t >> 5;
    const int n = blockIdx.x * 8 + w;
    const int k4 = lane * 4;

    float4 v  = *(const float4*)&g_accum[(size_t)n * DIM + k4];
    float4 cb = *(const float4*)&cbias[k4];
    v.x += cb.x; v.y += cb.y; v.z += cb.z; v.w += cb.w;

    float s = v.x + v.y + v.z + v.w;
    #pragma unroll
    for (int off = 16; off; off >>= 1) s += __shfl_xor_sync(0xffffffffu, s, off);
    const float mu = s * (1.0f / DIM);

    float d0 = v.x - mu, d1 = v.y - mu, d2 = v.z - mu, d3 = v.w - mu;
    float ss = d0 * d0 + d1 * d1 + d2 * d2 + d3 * d3;
    #pragma unroll
    for (int off = 16; off; off >>= 1) ss += __shfl_xor_sync(0xffffffffu, ss, off);
    const float rstd = rsqrtf(ss * (1.0f / DIM) + 1e-5f);

    float4 g  = *(const float4*)&gamma[k4];
    float4 b  = *(const float4*)&beta[k4];
    float4 xr = *(const float4*)&x[(size_t)n * DIM + k4];

    float o0 = fmaf(d0 * rstd, g.x, b.x); o0 = (o0 > 0.f ? o0 : 0.f) + xr.x;
    float o1 = fmaf(d1 * rstd, g.y, b.y); o1 = (o1 > 0.f ? o1 : 0.f) + xr.y;
    float o2 = fmaf(d2 * rstd, g.z, b.z); o2 = (o2 > 0.f ? o2 : 0.f) + xr.z;
    float o3 = fmaf(d3 * rstd, g.w, b.w); o3 = (o3 > 0.f ? o3 : 0.f) + xr.w;

    *(float4*)&out[(size_t)n * DIM + k4] = make_float4(o0, o1, o2, o3);
}

// ---------------- launch ----------------
extern "C" void kernel_launch(void* const* d_in, const int* in_sizes, int n_in,
                              void* d_out, int out_size) {
    const float* x    = (const float*)d_in[0];
    const void*  ei   = d_in[1];
    const float* eat  = (const float*)d_in[2];
    const float* Wl   = (const float*)d_in[3];
    const float* bl   = (const float*)d_in[4];
    const float* Wr   = (const float*)d_in[5];
    const float* br   = (const float*)d_in[6];
    const float* We   = (const float*)d_in[7];
    const float* att  = (const float*)d_in[8];
    const float* cb   = (const float*)d_in[9];
    const float* gam  = (const float*)d_in[10];
    const float* bet  = (const float*)d_in[11];
    float* out = (float*)d_out;

    k_detect<<<1, 32>>>(ei);
    k_zero<<<2048, 256>>>();
    k_gemm<<<NN / 16, 256>>>(x, Wl, bl, Wr, br);      // 3125 blocks
    k_logits<<<EE / 8, 256>>>(ei, eat, We, att);      // 200000 blocks
    k_exp<<<EE / 256, 256>>>(ei);                     // 6250 blocks
    k_aggr<<<EE / 8, 256>>>(ei);                      // 200000 blocks
    k_ln<<<NN / 8, 256>>>(x, cb, gam, bet, out);      // 6250 blocks
}

// round 12
// speedup vs baseline: 1.1647x; 1.1647x over previous
#include <cuda_runtime.h>
#include <stdint.h>

#define NN 50000
#define EE 1600000
#define DIM 128
#define HEADS 4
#define EDIM 16

// ---------------- scratch (device globals: allocation-free) ----------------
__device__ __align__(16) float g_xl[(size_t)NN * DIM];      // x @ W_l + b_l
__device__ __align__(16) float g_xr[(size_t)NN * DIM];      // x @ W_r + b_r
__device__ __align__(16) float g_logits[(size_t)EE * HEADS];// logits, then exp()
__device__ __align__(16) unsigned int g_menc[NN * HEADS];   // ordered-uint max
__device__ __align__(16) float g_denom[NN * HEADS];         // softmax denom
__device__ __align__(16) float g_accum[(size_t)NN * DIM];   // aggregated msgs
__device__ int g_idx64;                                     // edge_index dtype flag

// ---------------- helpers ----------------
__device__ __forceinline__ unsigned enc_f(float f) {
    unsigned u = __float_as_uint(f);
    return (u & 0x80000000u) ? ~u : (u | 0x80000000u);
}
__device__ __forceinline__ float dec_f(unsigned e) {
    return __uint_as_float((e & 0x80000000u) ? (e & 0x7FFFFFFFu) : ~e);
}
__device__ __forceinline__ void atomicAddF4(float* addr, float4 v) {
#if __CUDA_ARCH__ >= 900
    atomicAdd(reinterpret_cast<float4*>(addr), v);
#else
    atomicAdd(addr + 0, v.x); atomicAdd(addr + 1, v.y);
    atomicAdd(addr + 2, v.z); atomicAdd(addr + 3, v.w);
#endif
}
// packed f32x2 (Blackwell FFMA2 path — PTX-only)
__device__ __forceinline__ unsigned long long pk2(float lo, float hi) {
    unsigned long long r;
    asm("mov.b64 %0, {%1, %2};" : "=l"(r) : "f"(lo), "f"(hi));
    return r;
}
__device__ __forceinline__ unsigned long long fma2(unsigned long long a,
                                                   unsigned long long b,
                                                   unsigned long long c) {
    unsigned long long d;
    asm("fma.rn.f32x2 %0, %1, %2, %3;" : "=l"(d) : "l"(a), "l"(b), "l"(c));
    return d;
}
__device__ __forceinline__ float2 upk2(unsigned long long v) {
    float2 f;
    asm("mov.b64 {%0, %1}, %2;" : "=f"(f.x), "=f"(f.y) : "l"(v));
    return f;
}

// ---------------- K0: detect int64 vs int32 edge_index ----------------
__global__ void k_detect(const void* __restrict__ ei) {
    if (threadIdx.x == 0 && blockIdx.x == 0) {
        const long long* p = (const long long*)ei;
        int ok = 1;
        #pragma unroll 4
        for (int i = 0; i < 64; i++) {
            long long v = p[i];
            if (v < 0 || v >= NN) ok = 0;
        }
        g_idx64 = ok;
    }
}

// ---------------- K0b: zero accumulators ----------------
__global__ void k_zero() {
    size_t i = (size_t)blockIdx.x * blockDim.x + threadIdx.x;
    size_t stride = (size_t)gridDim.x * blockDim.x;
    for (size_t j = i; j < (size_t)NN * DIM; j += stride) g_accum[j] = 0.0f;
    for (size_t j = i; j < (size_t)NN * HEADS; j += stride) {
        g_denom[j] = 0.0f;
        g_menc[j] = 0u;   // below enc(-inf), never wins a max for real edges
    }
}

// ---------------- K1: fused GEMM  x@[W_l | W_r] + [b_l | b_r] ----------------
__global__ __launch_bounds__(256) void k_gemm(
    const float* __restrict__ x,
    const float* __restrict__ Wl, const float* __restrict__ bl,
    const float* __restrict__ Wr, const float* __restrict__ br)
{
    constexpr int KC = 32;
    __shared__ __align__(16) float Ws[KC][256];
    __shared__ __align__(16) float xs[KC][16];

    const int t  = threadIdx.x;
    const int cx = t & 63;        // col group: cols 4*cx .. 4*cx+3 (of 256)
    const int cy = t >> 6;        // row group: rows 4*cy .. 4*cy+3 (of 16)
    const int row0 = blockIdx.x * 16;

    float acc[4][4];
    #pragma unroll
    for (int i = 0; i < 4; i++)
        #pragma unroll
        for (int j = 0; j < 4; j++) acc[i][j] = 0.0f;

    for (int k0 = 0; k0 < DIM; k0 += KC) {
        #pragma unroll
        for (int i = t; i < KC * 64; i += 256) {
            int k  = i >> 6;
            int c4 = (i & 63) * 4;
            const float* srcp = (c4 < 128) ? &Wl[(k0 + k) * 128 + c4]
                                           : &Wr[(k0 + k) * 128 + (c4 - 128)];
            *(float4*)&Ws[k][c4] = *(const float4*)srcp;
        }
        if (t < 128) {
            int r  = t >> 3;
            int kq = (t & 7) * 4;
            float4 v = *(const float4*)&x[(size_t)(row0 + r) * DIM + k0 + kq];
            xs[kq + 0][r] = v.x; xs[kq + 1][r] = v.y;
            xs[kq + 2][r] = v.z; xs[kq + 3][r] = v.w;
        }
        __syncthreads();

        #pragma unroll
        for (int k = 0; k < KC; k++) {
            float4 w  = *(const float4*)&Ws[k][cx << 2];
            float4 xv = *(const float4*)&xs[k][cy << 2];
            acc[0][0] = fmaf(xv.x, w.x, acc[0][0]); acc[0][1] = fmaf(xv.x, w.y, acc[0][1]);
            acc[0][2] = fmaf(xv.x, w.z, acc[0][2]); acc[0][3] = fmaf(xv.x, w.w, acc[0][3]);
            acc[1][0] = fmaf(xv.y, w.x, acc[1][0]); acc[1][1] = fmaf(xv.y, w.y, acc[1][1]);
            acc[1][2] = fmaf(xv.y, w.z, acc[1][2]); acc[1][3] = fmaf(xv.y, w.w, acc[1][3]);
            acc[2][0] = fmaf(xv.z, w.x, acc[2][0]); acc[2][1] = fmaf(xv.z, w.y, acc[2][1]);
            acc[2][2] = fmaf(xv.z, w.z, acc[2][2]); acc[2][3] = fmaf(xv.z, w.w, acc[2][3]);
            acc[3][0] = fmaf(xv.w, w.x, acc[3][0]); acc[3][1] = fmaf(xv.w, w.y, acc[3][1]);
            acc[3][2] = fmaf(xv.w, w.z, acc[3][2]); acc[3][3] = fmaf(xv.w, w.w, acc[3][3]);
        }
        __syncthreads();
    }

    const int c4 = cx * 4;
    #pragma unroll
    for (int r = 0; r < 4; r++) {
        size_t row = (size_t)(row0 + cy * 4 + r);
        if (c4 < 128) {
            float4 o = make_float4(acc[r][0] + bl[c4],     acc[r][1] + bl[c4 + 1],
                                   acc[r][2] + bl[c4 + 2], acc[r][3] + bl[c4 + 3]);
            *(float4*)&g_xl[row * DIM + c4] = o;
        } else {
            int c = c4 - 128;
            float4 o = make_float4(acc[r][0] + br[c],     acc[r][1] + br[c + 1],
                                   acc[r][2] + br[c + 2], acc[r][3] + br[c + 3]);
            *(float4*)&g_xr[row * DIM + c] = o;
        }
    }
}

// ---------------- K2: edge attention logits + segment max (register W_e) -----
// Persistent warps; lane owns 4 consecutive channels of head (lane>>3).
// Zero shared memory in the hot loop: W_e slice + att live in registers,
// edge_attr is a warp-uniform broadcast load, ef uses packed f32x2 FMA.
__global__ __launch_bounds__(256, 2) void k_logits(
    const void* __restrict__ ei, const float* __restrict__ eattr,
    const float* __restrict__ We, const float* __restrict__ att)
{
    const int lane = threadIdx.x & 31;
    const int w    = threadIdx.x >> 5;
    const int h    = lane >> 3;                  // head 0..3
    const int ch   = h * 32 + (lane & 7) * 4;    // 4 consecutive channels

    // per-lane W_e slice (16 x 4), packed into f32x2 pairs: 32 u64 regs
    unsigned long long w01[EDIM], w23[EDIM];
    #pragma unroll
    for (int dd = 0; dd < EDIM; dd++) {
        float4 wv = *(const float4*)&We[dd * DIM + ch];
        w01[dd] = pk2(wv.x, wv.y);
        w23[dd] = pk2(wv.z, wv.w);
    }
    const float4 a4 = *(const float4*)&att[ch];

    const int is64 = g_idx64;
    const long long* p64 = (const long long*)ei;
    const int*       p32 = (const int*)ei;

    const int warpsTotal = gridDim.x * 8;
    for (int e = blockIdx.x * 8 + w; e < EE; e += warpsTotal) {
        int s = 0, d = 0;
        if (lane == 0) {
            if (is64) { s = (int)p64[e]; d = (int)p64[(size_t)EE + e]; }
            else      { s = p32[e];      d = p32[(size_t)EE + e]; }
        }
        s = __shfl_sync(0xffffffffu, s, 0);
        d = __shfl_sync(0xffffffffu, d, 0);

        // warp-uniform broadcast load of the 16 edge features
        const float4* ep = (const float4*)&eattr[(size_t)e * EDIM];
        float4 e0 = __ldg(ep + 0), e1 = __ldg(ep + 1);
        float4 e2 = __ldg(ep + 2), e3 = __ldg(ep + 3);
        float ea[EDIM] = { e0.x, e0.y, e0.z, e0.w,  e1.x, e1.y, e1.z, e1.w,
                           e2.x, e2.y, e2.z, e2.w,  e3.x, e3.y, e3.z, e3.w };

        unsigned long long ef01 = 0ull, ef23 = 0ull;   // packed {0,0}
        #pragma unroll
        for (int dd = 0; dd < EDIM; dd++) {
            unsigned long long aa = pk2(ea[dd], ea[dd]);
            ef01 = fma2(aa, w01[dd], ef01);
            ef23 = fma2(aa, w23[dd], ef23);
        }
        float2 f01 = upk2(ef01), f23 = upk2(ef23);

        float4 xlv = *(const float4*)&g_xl[(size_t)s * DIM + ch];
        float4 xrv = *(const float4*)&g_xr[(size_t)d * DIM + ch];

        float z0 = xlv.x + xrv.x + f01.x;
        float z1 = xlv.y + xrv.y + f01.y;
        float z2 = xlv.z + xrv.z + f23.x;
        float z3 = xlv.w + xrv.w + f23.y;
        z0 = fmaxf(z0, 0.2f * z0);
        z1 = fmaxf(z1, 0.2f * z1);
        z2 = fmaxf(z2, 0.2f * z2);
        z3 = fmaxf(z3, 0.2f * z3);

        float p = z0 * a4.x;
        p = fmaf(z1, a4.y, p);
        p = fmaf(z2, a4.z, p);
        p = fmaf(z3, a4.w, p);
        // reduce over the 8 lanes of this head
        p += __shfl_xor_sync(0xffffffffu, p, 4);
        p += __shfl_xor_sync(0xffffffffu, p, 2);
        p += __shfl_xor_sync(0xffffffffu, p, 1);

        if ((lane & 7) == 0) {
            g_logits[(size_t)e * HEADS + h] = p;
            atomicMax(&g_menc[d * HEADS + h], enc_f(p));
        }
    }
}

// ---------------- K3: exp(logit - m) + segment sum (denominator) ----------------
__global__ __launch_bounds__(256) void k_exp(const void* __restrict__ ei) {
    const int e = blockIdx.x * 256 + threadIdx.x;
    int d;
    if (g_idx64) d = (int)((const long long*)ei)[(size_t)EE + e];
    else         d = ((const int*)ei)[(size_t)EE + e];

    float4 lg = *((const float4*)g_logits + e);
    const unsigned* mp = &g_menc[d * HEADS];
    float4 ex = make_float4(expf(lg.x - dec_f(mp[0])),
                            expf(lg.y - dec_f(mp[1])),
                            expf(lg.z - dec_f(mp[2])),
                            expf(lg.w - dec_f(mp[3])));
    *((float4*)g_logits + e) = ex;
    atomicAddF4(&g_denom[d * HEADS], ex);
}

// ---------------- K4: weighted message aggregation ----------------
__global__ __launch_bounds__(256) void k_aggr(const void* __restrict__ ei) {
    const int t = threadIdx.x, lane = t & 31, w = t >> 5;
    const int e = blockIdx.x * 8 + w;
    int s = 0, d = 0;
    if (lane == 0) {
        if (g_idx64) {
            const long long* p = (const long long*)ei;
            s = (int)p[e]; d = (int)p[(size_t)EE + e];
        } else {
            const int* p = (const int*)ei;
            s = p[e]; d = p[(size_t)EE + e];
        }
    }
    s = __shfl_sync(0xffffffffu, s, 0);
    d = __shfl_sync(0xffffffffu, d, 0);

    const int h = lane >> 3;
    float ex  = __ldg(&g_logits[(size_t)e * HEADS + h]);
    float den = __ldg(&g_denom[d * HEADS + h]);
    float alpha = ex / (den + 1e-16f);

    float4 xv = *(const float4*)&g_xl[(size_t)s * DIM + lane * 4];
    float4 msg = make_float4(xv.x * alpha, xv.y * alpha, xv.z * alpha, xv.w * alpha);
    atomicAddF4(&g_accum[(size_t)d * DIM + lane * 4], msg);
}

// ---------------- K5: +bias, LayerNorm, ReLU, residual ----------------
__global__ __launch_bounds__(256) void k_ln(
    const float* __restrict__ x, const float* __restrict__ cbias,
    const float* __restrict__ gamma, const float* __restrict__ beta,
    float* __restrict__ out)
{
    const int t = threadIdx.x, lane = t & 31, w = t >> 5;
    const int n = blockIdx.x * 8 + w;
    const int k4 = lane * 4;

    float4 v  = *(const float4*)&g_accum[(size_t)n * DIM + k4];
    float4 cb = *(const float4*)&cbias[k4];
    v.x += cb.x; v.y += cb.y; v.z += cb.z; v.w += cb.w;

    float s = v.x + v.y + v.z + v.w;
    #pragma unroll
    for (int off = 16; off; off >>= 1) s += __shfl_xor_sync(0xffffffffu, s, off);
    const float mu = s * (1.0f / DIM);

    float d0 = v.x - mu, d1 = v.y - mu, d2 = v.z - mu, d3 = v.w - mu;
    float ss = d0 * d0 + d1 * d1 + d2 * d2 + d3 * d3;
    #pragma unroll
    for (int off = 16; off; off >>= 1) ss += __shfl_xor_sync(0xffffffffu, ss, off);
    const float rstd = rsqrtf(ss * (1.0f / DIM) + 1e-5f);

    float4 g  = *(const float4*)&gamma[k4];
    float4 b  = *(const float4*)&beta[k4];
    float4 xr = *(const float4*)&x[(size_t)n * DIM + k4];

    float o0 = fmaf(d0 * rstd, g.x, b.x); o0 = (o0 > 0.f ? o0 : 0.f) + xr.x;
    float o1 = fmaf(d1 * rstd, g.y, b.y); o1 = (o1 > 0.f ? o1 : 0.f) + xr.y;
    float o2 = fmaf(d2 * rstd, g.z, b.z); o2 = (o2 > 0.f ? o2 : 0.f) + xr.z;
    float o3 = fmaf(d3 * rstd, g.w, b.w); o3 = (o3 > 0.f ? o3 : 0.f) + xr.w;

    *(float4*)&out[(size_t)n * DIM + k4] = make_float4(o0, o1, o2, o3);
}

// ---------------- launch ----------------
extern "C" void kernel_launch(void* const* d_in, const int* in_sizes, int n_in,
                              void* d_out, int out_size) {
    const float* x    = (const float*)d_in[0];
    const void*  ei   = d_in[1];
    const float* eat  = (const float*)d_in[2];
    const float* Wl   = (const float*)d_in[3];
    const float* bl   = (const float*)d_in[4];
    const float* Wr   = (const float*)d_in[5];
    const float* br   = (const float*)d_in[6];
    const float* We   = (const float*)d_in[7];
    const float* att  = (const float*)d_in[8];
    const float* cb   = (const float*)d_in[9];
    const float* gam  = (const float*)d_in[10];
    const float* bet  = (const float*)d_in[11];
    float* out = (float*)d_out;

    k_detect<<<1, 32>>>(ei);
    k_zero<<<2048, 256>>>();
    k_gemm<<<NN / 16, 256>>>(x, Wl, bl, Wr, br);      // 3125 blocks
    k_logits<<<2960, 256>>>(ei, eat, We, att);        // persistent, 23680 warps
    k_exp<<<EE / 256, 256>>>(ei);                     // 6250 blocks
    k_aggr<<<EE / 8, 256>>>(ei);                      // 200000 blocks
    k_ln<<<NN / 8, 256>>>(x, cb, gam, bet, out);      // 6250 blocks
}

// round 13
// speedup vs baseline: 1.1673x; 1.0022x over previous
#include <cuda_runtime.h>
#include <stdint.h>

#define NN 50000
#define EE 1600000
#define DIM 128
#define HEADS 4
#define EDIM 16

// ---------------- scratch (device globals: allocation-free) ----------------
__device__ __align__(16) float g_xl[(size_t)NN * DIM];      // x @ W_l + b_l
__device__ __align__(16) float g_xr[(size_t)NN * DIM];      // x @ W_r + b_r
__device__ __align__(16) float g_logits[(size_t)EE * HEADS];// logits, then exp()
__device__ __align__(16) unsigned int g_menc[NN * HEADS];   // ordered-uint max
__device__ __align__(16) float g_denom[NN * HEADS];         // softmax denom
__device__ __align__(16) float g_accum[(size_t)NN * DIM];   // aggregated msgs
__device__ int g_idx64;                                     // edge_index dtype flag

// ---------------- helpers ----------------
__device__ __forceinline__ unsigned enc_f(float f) {
    unsigned u = __float_as_uint(f);
    return (u & 0x80000000u) ? ~u : (u | 0x80000000u);
}
__device__ __forceinline__ float dec_f(unsigned e) {
    return __uint_as_float((e & 0x80000000u) ? (e & 0x7FFFFFFFu) : ~e);
}
__device__ __forceinline__ void atomicAddF4(float* addr, float4 v) {
#if __CUDA_ARCH__ >= 900
    atomicAdd(reinterpret_cast<float4*>(addr), v);
#else
    atomicAdd(addr + 0, v.x); atomicAdd(addr + 1, v.y);
    atomicAdd(addr + 2, v.z); atomicAdd(addr + 3, v.w);
#endif
}
// packed f32x2 (Blackwell FFMA2 path — PTX-only)
__device__ __forceinline__ unsigned long long pk2(float lo, float hi) {
    unsigned long long r;
    asm("mov.b64 %0, {%1, %2};" : "=l"(r) : "f"(lo), "f"(hi));
    return r;
}
__device__ __forceinline__ unsigned long long fma2(unsigned long long a,
                                                   unsigned long long b,
                                                   unsigned long long c) {
    unsigned long long d;
    asm("fma.rn.f32x2 %0, %1, %2, %3;" : "=l"(d) : "l"(a), "l"(b), "l"(c));
    return d;
}
__device__ __forceinline__ float2 upk2(unsigned long long v) {
    float2 f;
    asm("mov.b64 {%0, %1}, %2;" : "=f"(f.x), "=f"(f.y) : "l"(v));
    return f;
}

// ---------------- K0: detect int64 vs int32 edge_index ----------------
__global__ void k_detect(const void* __restrict__ ei) {
    if (threadIdx.x == 0 && blockIdx.x == 0) {
        const long long* p = (const long long*)ei;
        int ok = 1;
        #pragma unroll 4
        for (int i = 0; i < 64; i++) {
            long long v = p[i];
            if (v < 0 || v >= NN) ok = 0;
        }
        g_idx64 = ok;
    }
}

// ---------------- K0b: zero accumulators ----------------
__global__ void k_zero() {
    size_t i = (size_t)blockIdx.x * blockDim.x + threadIdx.x;
    size_t stride = (size_t)gridDim.x * blockDim.x;
    for (size_t j = i; j < (size_t)NN * DIM; j += stride) g_accum[j] = 0.0f;
    for (size_t j = i; j < (size_t)NN * HEADS; j += stride) {
        g_denom[j] = 0.0f;
        g_menc[j] = 0u;   // below enc(-inf), never wins a max for real edges
    }
}

// ---------------- K1: fused GEMM  x@[W_l | W_r] + [b_l | b_r] ----------------
__global__ __launch_bounds__(256) void k_gemm(
    const float* __restrict__ x,
    const float* __restrict__ Wl, const float* __restrict__ bl,
    const float* __restrict__ Wr, const float* __restrict__ br)
{
    constexpr int KC = 32;
    __shared__ __align__(16) float Ws[KC][256];
    __shared__ __align__(16) float xs[KC][16];

    const int t  = threadIdx.x;
    const int cx = t & 63;        // col group: cols 4*cx .. 4*cx+3 (of 256)
    const int cy = t >> 6;        // row group: rows 4*cy .. 4*cy+3 (of 16)
    const int row0 = blockIdx.x * 16;

    float acc[4][4];
    #pragma unroll
    for (int i = 0; i < 4; i++)
        #pragma unroll
        for (int j = 0; j < 4; j++) acc[i][j] = 0.0f;

    for (int k0 = 0; k0 < DIM; k0 += KC) {
        #pragma unroll
        for (int i = t; i < KC * 64; i += 256) {
            int k  = i >> 6;
            int c4 = (i & 63) * 4;
            const float* srcp = (c4 < 128) ? &Wl[(k0 + k) * 128 + c4]
                                           : &Wr[(k0 + k) * 128 + (c4 - 128)];
            *(float4*)&Ws[k][c4] = *(const float4*)srcp;
        }
        if (t < 128) {
            int r  = t >> 3;
            int kq = (t & 7) * 4;
            float4 v = *(const float4*)&x[(size_t)(row0 + r) * DIM + k0 + kq];
            xs[kq + 0][r] = v.x; xs[kq + 1][r] = v.y;
            xs[kq + 2][r] = v.z; xs[kq + 3][r] = v.w;
        }
        __syncthreads();

        #pragma unroll
        for (int k = 0; k < KC; k++) {
            float4 w  = *(const float4*)&Ws[k][cx << 2];
            float4 xv = *(const float4*)&xs[k][cy << 2];
            acc[0][0] = fmaf(xv.x, w.x, acc[0][0]); acc[0][1] = fmaf(xv.x, w.y, acc[0][1]);
            acc[0][2] = fmaf(xv.x, w.z, acc[0][2]); acc[0][3] = fmaf(xv.x, w.w, acc[0][3]);
            acc[1][0] = fmaf(xv.y, w.x, acc[1][0]); acc[1][1] = fmaf(xv.y, w.y, acc[1][1]);
            acc[1][2] = fmaf(xv.y, w.z, acc[1][2]); acc[1][3] = fmaf(xv.y, w.w, acc[1][3]);
            acc[2][0] = fmaf(xv.z, w.x, acc[2][0]); acc[2][1] = fmaf(xv.z, w.y, acc[2][1]);
            acc[2][2] = fmaf(xv.z, w.z, acc[2][2]); acc[2][3] = fmaf(xv.z, w.w, acc[2][3]);
            acc[3][0] = fmaf(xv.w, w.x, acc[3][0]); acc[3][1] = fmaf(xv.w, w.y, acc[3][1]);
            acc[3][2] = fmaf(xv.w, w.z, acc[3][2]); acc[3][3] = fmaf(xv.w, w.w, acc[3][3]);
        }
        __syncthreads();
    }

    const int c4 = cx * 4;
    #pragma unroll
    for (int r = 0; r < 4; r++) {
        size_t row = (size_t)(row0 + cy * 4 + r);
        if (c4 < 128) {
            float4 o = make_float4(acc[r][0] + bl[c4],     acc[r][1] + bl[c4 + 1],
                                   acc[r][2] + bl[c4 + 2], acc[r][3] + bl[c4 + 3]);
            *(float4*)&g_xl[row * DIM + c4] = o;
        } else {
            int c = c4 - 128;
            float4 o = make_float4(acc[r][0] + br[c],     acc[r][1] + br[c + 1],
                                   acc[r][2] + br[c + 2], acc[r][3] + br[c + 3]);
            *(float4*)&g_xr[row * DIM + c] = o;
        }
    }
}

// ---------------- K2: edge attention logits + segment max (register W_e) -----
// Persistent warps; lane owns 4 consecutive channels of head (lane>>3).
// Zero shared memory in the hot loop: W_e slice + att live in registers,
// edge_attr is a warp-uniform broadcast load, ef uses packed f32x2 FMA.
__global__ __launch_bounds__(256, 2) void k_logits(
    const void* __restrict__ ei, const float* __restrict__ eattr,
    const float* __restrict__ We, const float* __restrict__ att)
{
    const int lane = threadIdx.x & 31;
    const int w    = threadIdx.x >> 5;
    const int h    = lane >> 3;                  // head 0..3
    const int ch   = h * 32 + (lane & 7) * 4;    // 4 consecutive channels

    // per-lane W_e slice (16 x 4), packed into f32x2 pairs: 32 u64 regs
    unsigned long long w01[EDIM], w23[EDIM];
    #pragma unroll
    for (int dd = 0; dd < EDIM; dd++) {
        float4 wv = *(const float4*)&We[dd * DIM + ch];
        w01[dd] = pk2(wv.x, wv.y);
        w23[dd] = pk2(wv.z, wv.w);
    }
    const float4 a4 = *(const float4*)&att[ch];

    const int is64 = g_idx64;
    const long long* p64 = (const long long*)ei;
    const int*       p32 = (const int*)ei;

    const int warpsTotal = gridDim.x * 8;
    for (int e = blockIdx.x * 8 + w; e < EE; e += warpsTotal) {
        int s = 0, d = 0;
        if (lane == 0) {
            if (is64) { s = (int)p64[e]; d = (int)p64[(size_t)EE + e]; }
            else      { s = p32[e];      d = p32[(size_t)EE + e]; }
        }
        s = __shfl_sync(0xffffffffu, s, 0);
        d = __shfl_sync(0xffffffffu, d, 0);

        // warp-uniform broadcast load of the 16 edge features
        const float4* ep = (const float4*)&eattr[(size_t)e * EDIM];
        float4 e0 = __ldg(ep + 0), e1 = __ldg(ep + 1);
        float4 e2 = __ldg(ep + 2), e3 = __ldg(ep + 3);
        float ea[EDIM] = { e0.x, e0.y, e0.z, e0.w,  e1.x, e1.y, e1.z, e1.w,
                           e2.x, e2.y, e2.z, e2.w,  e3.x, e3.y, e3.z, e3.w };

        unsigned long long ef01 = 0ull, ef23 = 0ull;   // packed {0,0}
        #pragma unroll
        for (int dd = 0; dd < EDIM; dd++) {
            unsigned long long aa = pk2(ea[dd], ea[dd]);
            ef01 = fma2(aa, w01[dd], ef01);
            ef23 = fma2(aa, w23[dd], ef23);
        }
        float2 f01 = upk2(ef01), f23 = upk2(ef23);

        float4 xlv = *(const float4*)&g_xl[(size_t)s * DIM + ch];
        float4 xrv = *(const float4*)&g_xr[(size_t)d * DIM + ch];

        float z0 = xlv.x + xrv.x + f01.x;
        float z1 = xlv.y + xrv.y + f01.y;
        float z2 = xlv.z + xrv.z + f23.x;
        float z3 = xlv.w + xrv.w + f23.y;
        z0 = fmaxf(z0, 0.2f * z0);
        z1 = fmaxf(z1, 0.2f * z1);
        z2 = fmaxf(z2, 0.2f * z2);
        z3 = fmaxf(z3, 0.2f * z3);

        float p = z0 * a4.x;
        p = fmaf(z1, a4.y, p);
        p = fmaf(z2, a4.z, p);
        p = fmaf(z3, a4.w, p);
        // reduce over the 8 lanes of this head
        p += __shfl_xor_sync(0xffffffffu, p, 4);
        p += __shfl_xor_sync(0xffffffffu, p, 2);
        p += __shfl_xor_sync(0xffffffffu, p, 1);

        if ((lane & 7) == 0) {
            g_logits[(size_t)e * HEADS + h] = p;
            atomicMax(&g_menc[d * HEADS + h], enc_f(p));
        }
    }
}

// ---------------- K3: exp(logit - m) + segment sum (denominator) ----------------
__global__ __launch_bounds__(256) void k_exp(const void* __restrict__ ei) {
    const int e = blockIdx.x * 256 + threadIdx.x;
    int d;
    if (g_idx64) d = (int)((const long long*)ei)[(size_t)EE + e];
    else         d = ((const int*)ei)[(size_t)EE + e];

    float4 lg = *((const float4*)g_logits + e);
    const unsigned* mp = &g_menc[d * HEADS];
    float4 ex = make_float4(expf(lg.x - dec_f(mp[0])),
                            expf(lg.y - dec_f(mp[1])),
                            expf(lg.z - dec_f(mp[2])),
                            expf(lg.w - dec_f(mp[3])));
    *((float4*)g_logits + e) = ex;
    atomicAddF4(&g_denom[d * HEADS], ex);
}

// ---------------- K4: weighted message aggregation ----------------
__global__ __launch_bounds__(256) void k_aggr(const void* __restrict__ ei) {
    const int t = threadIdx.x, lane = t & 31, w = t >> 5;
    const int e = blockIdx.x * 8 + w;
    int s = 0, d = 0;
    if (lane == 0) {
        if (g_idx64) {
            const long long* p = (const long long*)ei;
            s = (int)p[e]; d = (int)p[(size_t)EE + e];
        } else {
            const int* p = (const int*)ei;
            s = p[e]; d = p[(size_t)EE + e];
        }
    }
    s = __shfl_sync(0xffffffffu, s, 0);
    d = __shfl_sync(0xffffffffu, d, 0);

    const int h = lane >> 3;
    float ex  = __ldg(&g_logits[(size_t)e * HEADS + h]);
    float den = __ldg(&g_denom[d * HEADS + h]);
    float alpha = ex / (den + 1e-16f);

    float4 xv = *(const float4*)&g_xl[(size_t)s * DIM + lane * 4];
    float4 msg = make_float4(xv.x * alpha, xv.y * alpha, xv.z * alpha, xv.w * alpha);
    atomicAddF4(&g_accum[(size_t)d * DIM + lane * 4], msg);
}

// ---------------- K5: +bias, LayerNorm, ReLU, residual ----------------
__global__ __launch_bounds__(256) void k_ln(
    const float* __restrict__ x, const float* __restrict__ cbias,
    const float* __restrict__ gamma, const float* __restrict__ beta,
    float* __restrict__ out)
{
    const int t = threadIdx.x, lane = t & 31, w = t >> 5;
    const int n = blockIdx.x * 8 + w;
    const int k4 = lane * 4;

    float4 v  = *(const float4*)&g_accum[(size_t)n * DIM + k4];
    float4 cb = *(const float4*)&cbias[k4];
    v.x += cb.x; v.y += cb.y; v.z += cb.z; v.w += cb.w;

    float s = v.x + v.y + v.z + v.w;
    #pragma unroll
    for (int off = 16; off; off >>= 1) s += __shfl_xor_sync(0xffffffffu, s, off);
    const float mu = s * (1.0f / DIM);

    float d0 = v.x - mu, d1 = v.y - mu, d2 = v.z - mu, d3 = v.w - mu;
    float ss = d0 * d0 + d1 * d1 + d2 * d2 + d3 * d3;
    #pragma unroll
    for (int off = 16; off; off >>= 1) ss += __shfl_xor_sync(0xffffffffu, ss, off);
    const float rstd = rsqrtf(ss * (1.0f / DIM) + 1e-5f);

    float4 g  = *(const float4*)&gamma[k4];
    float4 b  = *(const float4*)&beta[k4];
    float4 xr = *(const float4*)&x[(size_t)n * DIM + k4];

    float o0 = fmaf(d0 * rstd, g.x, b.x); o0 = (o0 > 0.f ? o0 : 0.f) + xr.x;
    float o1 = fmaf(d1 * rstd, g.y, b.y); o1 = (o1 > 0.f ? o1 : 0.f) + xr.y;
    float o2 = fmaf(d2 * rstd, g.z, b.z); o2 = (o2 > 0.f ? o2 : 0.f) + xr.z;
    float o3 = fmaf(d3 * rstd, g.w, b.w); o3 = (o3 > 0.f ? o3 : 0.f) + xr.w;

    *(float4*)&out[(size_t)n * DIM + k4] = make_float4(o0, o1, o2, o3);
}

// ---------------- launch ----------------
extern "C" void kernel_launch(void* const* d_in, const int* in_sizes, int n_in,
                              void* d_out, int out_size) {
    const float* x    = (const float*)d_in[0];
    const void*  ei   = d_in[1];
    const float* eat  = (const float*)d_in[2];
    const float* Wl   = (const float*)d_in[3];
    const float* bl   = (const float*)d_in[4];
    const float* Wr   = (const float*)d_in[5];
    const float* br   = (const float*)d_in[6];
    const float* We   = (const float*)d_in[7];
    const float* att  = (const float*)d_in[8];
    const float* cb   = (const float*)d_in[9];
    const float* gam  = (const float*)d_in[10];
    const float* bet  = (const float*)d_in[11];
    float* out = (float*)d_out;

    k_detect<<<1, 32>>>(ei);
    k_zero<<<2048, 256>>>();
    k_gemm<<<NN / 16, 256>>>(x, Wl, bl, Wr, br);      // 3125 blocks
    k_logits<<<2960, 256>>>(ei, eat, We, att);        // persistent, 23680 warps
    k_exp<<<EE / 256, 256>>>(ei);                     // 6250 blocks
    k_aggr<<<EE / 8, 256>>>(ei);                      // 200000 blocks
    k_ln<<<NN / 8, 256>>>(x, cb, gam, bet, out);      // 6250 blocks
}